// round 4
// baseline (speedup 1.0000x reference)
#include <cuda_runtime.h>
#include <cstdint>

#define LMAX  8
#define NSH   81   // (LMAX+1)^2
#define NF    45   // (LMAX+1)(LMAX+2)/2
#define TILE  128
#define NWARP (TILE / 32)
#define HALF_PTS   16
#define HALF_BYTES (HALF_PTS * NSH * 4)   // 5184 B, %16 == 0

__global__ __launch_bounds__(TILE)
void sh_kernel(const float* __restrict__ xyz,
               const float* __restrict__ F,
               float* __restrict__ out,
               int n)
{
    // One 16-point staging buffer per warp, reused for both halves.
    __shared__ __align__(16) float s_out[NWARP * HALF_PTS * NSH];
    __shared__ float s_F[NF];

    const int tid  = threadIdx.x;
    const int lane = tid & 31;
    const int warp = tid >> 5;

    if (tid < NF) s_F[tid] = F[tid];
    __syncthreads();

    const int base_pt   = blockIdx.x * TILE;
    const int warp_base = base_pt + warp * 32;   // 32 points per warp
    const int p         = warp_base + lane;      // this lane's point

    float x = 0.0f, y = 0.0f, z = 1.0f;
    if (p < n) {
        x = xyz[3 * p + 0];
        y = xyz[3 * p + 1];
        z = xyz[3 * p + 2];
    }
    const float rinv = rsqrtf(x * x + y * y + z * z);
    x *= rinv; y *= rinv; z *= rinv;

    // Associated-Legendre recurrence (flattened triangular), fully unrolled.
    float Q[NF];
    Q[0] = 1.0f;
    #pragma unroll
    for (int l = 1; l <= LMAX; ++l) {
        const int b   = l * (l + 1) / 2;
        const int bp  = (l - 1) * l / 2;
        const int bpp = (l - 2) * (l - 1) / 2;   // unused when l==1
        Q[b + l]     = -(2.0f * l - 1.0f) * Q[bp + (l - 1)];
        Q[b + l - 1] = -z * Q[b + l];
        #pragma unroll
        for (int m = 0; m <= l - 2; ++m) {
            Q[b + m] = ((2.0f * l - 1.0f) * z * Q[bp + m]
                        - (float)(l + m - 1) * Q[bpp + m])
                       * (1.0f / (float)(l - m));
        }
    }
    // Fold the normalization constants in once: Q[i] <- F[i]*Q[i].
    #pragma unroll
    for (int i = 0; i < NF; ++i) Q[i] *= s_F[i];

    float sv[LMAX + 1], cv[LMAX + 1];
    sv[0] = 0.0f; cv[0] = 1.0f;
    #pragma unroll
    for (int m = 1; m <= LMAX; ++m) {
        sv[m] = x * sv[m - 1] + y * cv[m - 1];
        cv[m] = x * cv[m - 1] - y * sv[m - 1];
    }

    const float inv_sqrt2 = 0.70710678118654752440f;
    float* const warp_buf = s_out + warp * (HALF_PTS * NSH);

    // Two phases through one buffer: lanes [16h, 16h+16) stage, lane 0 TMA-stores.
    #pragma unroll
    for (int half = 0; half < 2; ++half) {
        const int chunk_base = warp_base + half * HALF_PTS;

        if ((lane >> 4) == half && p < n) {
            // stride 81 -> bank (17*i + c) mod 32 is a lane permutation: conflict-free
            float* row = warp_buf + (lane & 15) * NSH;
            #pragma unroll
            for (int l = 0; l <= LMAX; ++l) {
                const int b  = l * (l + 1) / 2;
                const int cb = l * l;
                #pragma unroll
                for (int k = l; k >= 1; --k)          // m = -l .. -1
                    row[cb + l - k] = Q[b + k] * sv[k];
                row[cb + l] = Q[b] * inv_sqrt2;       // m = 0
                #pragma unroll
                for (int m = 1; m <= l; ++m)          // m = 1 .. l
                    row[cb + l + m] = Q[b + m] * cv[m];
            }
        }
        __syncwarp();   // staging visible warp-wide before TMA / scalar copy

        const int valid = min(HALF_PTS, n - chunk_base);
        if (valid == HALF_PTS) {
            if (lane == 0) {
                asm volatile("fence.proxy.async.shared::cta;" ::: "memory");
                uint32_t src = (uint32_t)__cvta_generic_to_shared(warp_buf);
                float* dst   = out + (long long)chunk_base * NSH;
                asm volatile(
                    "cp.async.bulk.global.shared::cta.bulk_group [%0], [%1], %2;"
                    :: "l"(dst), "r"(src), "n"(HALF_BYTES) : "memory");
                asm volatile("cp.async.bulk.commit_group;" ::: "memory");
                // Drain before the buffer is overwritten (half 0) or we exit (half 1).
                asm volatile("cp.async.bulk.wait_group 0;" ::: "memory");
            }
        } else if (valid > 0) {
            // Tail path (never hit for n % 16 == 0, kept for correctness).
            const int total = valid * NSH;
            float* dst = out + (long long)chunk_base * NSH;
            for (int i = lane; i < total; i += 32)
                dst[i] = warp_buf[i];
        }
        __syncwarp();   // all lanes see the drain before buffer reuse
    }
}

extern "C" void kernel_launch(void* const* d_in, const int* in_sizes, int n_in,
                              void* d_out, int out_size)
{
    const float* xyz = (const float*)d_in[0];
    const float* F   = (const float*)d_in[1];
    float* out       = (float*)d_out;
    const int n = in_sizes[0] / 3;
    const int grid = (n + TILE - 1) / TILE;
    sh_kernel<<<grid, TILE>>>(xyz, F, out, n);
}